// round 4
// baseline (speedup 1.0000x reference)
#include <cuda_runtime.h>
#include <math.h>

#define N_NODES 50000
#define F_IN    500
#define NEDGE   800000

// ---------------- scratch (device globals: no allocation allowed) ----------
__device__ float g_h  [N_NODES * 128];   // GEMM output / logits reuse
__device__ float g_als[N_NODES * 2];
__device__ float g_ald[N_NODES * 2];
__device__ float g_s0 [N_NODES * 128];
__device__ float g_s1 [N_NODES * 128];
__device__ float g_s2 [N_NODES * 128];
__device__ float g_x  [N_NODES * 128];   // layer-0 output / layer-1 input
__device__ int   g_rowptr[3][N_NODES + 1];
__device__ int   g_csrc  [3][NEDGE];
__device__ int   g_fill  [N_NODES];

// ---------------- helpers ---------------------------------------------------
__device__ __forceinline__ float lrelu(float x) { return x > 0.f ? x : 0.2f * x; }
__device__ __forceinline__ float eluf (float x) { return x > 0.f ? x : expm1f(x); }

#define PACK2(d, x, y)  asm("mov.b64 %0, {%1,%2};"      : "=l"(d) : "f"(x), "f"(y))
#define UNPACK2(x, y, d) asm("mov.b64 {%0,%1}, %2;"     : "=f"(x), "=f"(y) : "l"(d))
#define FMA2(d, a, b)   asm("fma.rn.f32x2 %0, %1, %2, %0;" : "+l"(d) : "l"(a), "l"(b))

// ---------------- SGEMM: C[M,Nn] = A[M,K] @ B[K,Nn]  (fp32, f32x2 FMA) -----
// BM=128, BN=128, BK=8, 256 threads, 8x8 per thread.
__global__ __launch_bounds__(256, 2)
void k_gemm(const float* __restrict__ A, const float* __restrict__ B,
            float* __restrict__ C, int M, int K, int Nn)
{
    __shared__ float As[8][128];
    __shared__ float Bs[8][128];
    const int tid  = threadIdx.x;
    const int bm   = blockIdx.y * 128;
    const int bn   = blockIdx.x * 128;
    const int row0 = (tid >> 4) * 8;
    const int col0 = (tid & 15) * 8;

    unsigned long long acc[8][4];
#pragma unroll
    for (int i = 0; i < 8; ++i)
#pragma unroll
        for (int j = 0; j < 4; ++j) acc[i][j] = 0ull;

    const int arow = tid >> 1;
    const int akq  = (tid & 1) * 4;
    const int bkk  = tid >> 5;
    const int bcol = (tid & 31) * 4;
    const int gr   = bm + arow;

    for (int k0 = 0; k0 < K; k0 += 8) {
        float4 av;
        if (gr < M && k0 + akq + 4 <= K) {
            av = *reinterpret_cast<const float4*>(A + (size_t)gr * K + k0 + akq);
        } else {
            av.x = (gr < M && k0 + akq + 0 < K) ? A[(size_t)gr * K + k0 + akq + 0] : 0.f;
            av.y = (gr < M && k0 + akq + 1 < K) ? A[(size_t)gr * K + k0 + akq + 1] : 0.f;
            av.z = (gr < M && k0 + akq + 2 < K) ? A[(size_t)gr * K + k0 + akq + 2] : 0.f;
            av.w = (gr < M && k0 + akq + 3 < K) ? A[(size_t)gr * K + k0 + akq + 3] : 0.f;
        }
        As[akq + 0][arow] = av.x; As[akq + 1][arow] = av.y;
        As[akq + 2][arow] = av.z; As[akq + 3][arow] = av.w;

        float4 bv;
        const int gk = k0 + bkk;
        if (gk < K && bn + bcol + 4 <= Nn) {
            bv = *reinterpret_cast<const float4*>(B + (size_t)gk * Nn + bn + bcol);
        } else {
            bv.x = (gk < K && bn + bcol + 0 < Nn) ? B[(size_t)gk * Nn + bn + bcol + 0] : 0.f;
            bv.y = (gk < K && bn + bcol + 1 < Nn) ? B[(size_t)gk * Nn + bn + bcol + 1] : 0.f;
            bv.z = (gk < K && bn + bcol + 2 < Nn) ? B[(size_t)gk * Nn + bn + bcol + 2] : 0.f;
            bv.w = (gk < K && bn + bcol + 3 < Nn) ? B[(size_t)gk * Nn + bn + bcol + 3] : 0.f;
        }
        *reinterpret_cast<float4*>(&Bs[bkk][bcol]) = bv;
        __syncthreads();

#pragma unroll
        for (int kk = 0; kk < 8; ++kk) {
            float4 a0 = *reinterpret_cast<const float4*>(&As[kk][row0]);
            float4 a1 = *reinterpret_cast<const float4*>(&As[kk][row0 + 4]);
            float4 b0 = *reinterpret_cast<const float4*>(&Bs[kk][col0]);
            float4 b1 = *reinterpret_cast<const float4*>(&Bs[kk][col0 + 4]);
            unsigned long long bp[4], ap;
            PACK2(bp[0], b0.x, b0.y); PACK2(bp[1], b0.z, b0.w);
            PACK2(bp[2], b1.x, b1.y); PACK2(bp[3], b1.z, b1.w);
            float ar[8] = {a0.x, a0.y, a0.z, a0.w, a1.x, a1.y, a1.z, a1.w};
#pragma unroll
            for (int i = 0; i < 8; ++i) {
                PACK2(ap, ar[i], ar[i]);
                FMA2(acc[i][0], ap, bp[0]);
                FMA2(acc[i][1], ap, bp[1]);
                FMA2(acc[i][2], ap, bp[2]);
                FMA2(acc[i][3], ap, bp[3]);
            }
        }
        __syncthreads();
    }

#pragma unroll
    for (int i = 0; i < 8; ++i) {
        int r = bm + row0 + i;
        if (r >= M) break;
        float v[8];
        UNPACK2(v[0], v[1], acc[i][0]);
        UNPACK2(v[2], v[3], acc[i][1]);
        UNPACK2(v[4], v[5], acc[i][2]);
        UNPACK2(v[6], v[7], acc[i][3]);
        if (bn + col0 + 8 <= Nn) {
            *reinterpret_cast<float4*>(C + (size_t)r * Nn + bn + col0)     = make_float4(v[0], v[1], v[2], v[3]);
            *reinterpret_cast<float4*>(C + (size_t)r * Nn + bn + col0 + 4) = make_float4(v[4], v[5], v[6], v[7]);
        } else {
#pragma unroll
            for (int j = 0; j < 8; ++j) {
                int c = bn + col0 + j;
                if (c < Nn) C[(size_t)r * Nn + c] = v[j];
            }
        }
    }
}

// ---------------- attention logit pre-reduction: al_s, al_d [N,2] ----------
__global__ void k_al(const float* __restrict__ h, const float* __restrict__ a_s,
                     const float* __restrict__ a_d, float* __restrict__ als,
                     float* __restrict__ ald, int C)
{
    int w = (blockIdx.x * blockDim.x + threadIdx.x) >> 5;
    if (w >= N_NODES) return;
    int lane = threadIdx.x & 31;
    int HC = 2 * C;
#pragma unroll
    for (int hh = 0; hh < 2; ++hh) {
        float ss = 0.f, sd = 0.f;
        for (int c = lane; c < C; c += 32) {
            float v = h[(size_t)w * HC + hh * C + c];
            ss += v * __ldg(a_s + hh * C + c);
            sd += v * __ldg(a_d + hh * C + c);
        }
#pragma unroll
        for (int o = 16; o; o >>= 1) {
            ss += __shfl_xor_sync(~0u, ss, o);
            sd += __shfl_xor_sync(~0u, sd, o);
        }
        if (lane == 0) { als[w * 2 + hh] = ss; ald[w * 2 + hh] = sd; }
    }
}

// ---------------- fused GAT aggregation: online softmax over CSR -----------
// One warp per dst node; lane owns 4 channels (float4). Self loop included.
__global__ void k_gat(const float* __restrict__ h, const float* __restrict__ als,
                      const float* __restrict__ ald, const int* __restrict__ rowptr,
                      const int* __restrict__ csrc, const float* __restrict__ bias,
                      float* __restrict__ out, int C, int concat)
{
    int n = (blockIdx.x * blockDim.x + threadIdx.x) >> 5;
    if (n >= N_NODES) return;
    const int lane = threadIdx.x & 31;
    const int HC   = 2 * C;
    const int idx  = lane * 4;
    const bool act = idx < HC;
    const int head = (idx >= C) ? 1 : 0;

    const float adh = ald[n * 2 + head];
    float m   = lrelu(als[n * 2 + head] + adh);   // self-loop logit
    float den = 1.f;                              // exp(e_self - m) = 1
    float4 acc = make_float4(0.f, 0.f, 0.f, 0.f);
    if (act) acc = *reinterpret_cast<const float4*>(h + (size_t)n * HC + idx);

    const int p0 = rowptr[n], p1 = rowptr[n + 1];
    for (int p = p0; p < p1; ++p) {
        int s = csrc[p];
        float e  = lrelu(als[s * 2 + head] + adh);
        float nm = fmaxf(m, e);
        float sc = __expf(m - nm);
        float wg = __expf(e - nm);
        den = den * sc + wg;
        m = nm;
        if (act) {
            float4 hv = *reinterpret_cast<const float4*>(h + (size_t)s * HC + idx);
            acc.x = fmaf(acc.x, sc, wg * hv.x);
            acc.y = fmaf(acc.y, sc, wg * hv.y);
            acc.z = fmaf(acc.z, sc, wg * hv.z);
            acc.w = fmaf(acc.w, sc, wg * hv.w);
        }
    }
    float inv = 1.f / (den + 1e-16f);
    float4 v = make_float4(acc.x * inv, acc.y * inv, acc.z * inv, acc.w * inv);

    if (concat) {
        if (act) {
            const float4 b = *reinterpret_cast<const float4*>(bias + idx);
            float4 r;
            r.x = eluf(v.x + b.x); r.y = eluf(v.y + b.y);
            r.z = eluf(v.z + b.z); r.w = eluf(v.w + b.w);
            *reinterpret_cast<float4*>(out + (size_t)n * HC + idx) = r;
        }
    } else {
        int half = C / 4;  // lanes [half, 2*half) hold head 1
        float ox = __shfl_down_sync(~0u, v.x, half);
        float oy = __shfl_down_sync(~0u, v.y, half);
        float oz = __shfl_down_sync(~0u, v.z, half);
        float ow = __shfl_down_sync(~0u, v.w, half);
        if (idx < C) {
            const float4 b = *reinterpret_cast<const float4*>(bias + idx);
            float4 r;
            r.x = eluf(0.5f * (v.x + ox) + b.x);
            r.y = eluf(0.5f * (v.y + oy) + b.y);
            r.z = eluf(0.5f * (v.z + oz) + b.z);
            r.w = eluf(0.5f * (v.w + ow) + b.w);
            *reinterpret_cast<float4*>(out + (size_t)n * C + idx) = r;
        }
    }
}

// ---------------- order mixing: out = sum_j wf[j] * elu(sum_k s_k * W[k,j]) -
__global__ void k_mix(const float* __restrict__ s0, const float* __restrict__ s1,
                      const float* __restrict__ s2, const float* __restrict__ Wm,
                      const float* __restrict__ wf, float* __restrict__ out, int NC)
{
    int i = blockIdx.x * blockDim.x + threadIdx.x;
    if (i >= NC) return;
    float a = s0[i], b = s1[i], c = s2[i];
    float m0 = eluf(a * __ldg(Wm + 0) + b * __ldg(Wm + 3) + c * __ldg(Wm + 6));
    float m1 = eluf(a * __ldg(Wm + 1) + b * __ldg(Wm + 4) + c * __ldg(Wm + 7));
    float m2 = eluf(a * __ldg(Wm + 2) + b * __ldg(Wm + 5) + c * __ldg(Wm + 8));
    out[i] = m0 * __ldg(wf + 0) + m1 * __ldg(wf + 1) + m2 * __ldg(wf + 2);
}

// ---------------- row log-softmax over 40 classes ---------------------------
__global__ void k_lsm(const float* __restrict__ x, float* __restrict__ out)
{
    int n = (blockIdx.x * blockDim.x + threadIdx.x) >> 5;
    if (n >= N_NODES) return;
    int lane = threadIdx.x & 31;
    float v0 = (lane < 40)      ? x[(size_t)n * 40 + lane]      : -1e30f;
    float v1 = (lane + 32 < 40) ? x[(size_t)n * 40 + lane + 32] : -1e30f;
    float mx = fmaxf(v0, v1);
#pragma unroll
    for (int o = 16; o; o >>= 1) mx = fmaxf(mx, __shfl_xor_sync(~0u, mx, o));
    float s = 0.f;
    if (lane < 40)      s += expf(v0 - mx);
    if (lane + 32 < 40) s += expf(v1 - mx);
#pragma unroll
    for (int o = 16; o; o >>= 1) s += __shfl_xor_sync(~0u, s, o);
    float lse = logf(s) + mx;
    if (lane < 40)      out[(size_t)n * 40 + lane]      = v0 - lse;
    if (lane + 32 < 40) out[(size_t)n * 40 + lane + 32] = v1 - lse;
}

// ---------------- CSR build --------------------------------------------------
__global__ void k_zero(int* p, int n)
{
    int i = blockIdx.x * blockDim.x + threadIdx.x;
    if (i < n) p[i] = 0;
}

__global__ void k_count(const int* __restrict__ ei, int* __restrict__ cnt)
{
    int i = blockIdx.x * blockDim.x + threadIdx.x;
    if (i < NEDGE) atomicAdd(&cnt[ei[NEDGE + i] + 1], 1);
}

__global__ void k_scan(int* a, int n)
{
    __shared__ int sh[1024];
    __shared__ int carry;
    if (threadIdx.x == 0) carry = 0;
    __syncthreads();
    for (int base = 0; base < n; base += 1024) {
        int i = base + threadIdx.x;
        int v = (i < n) ? a[i] : 0;
        sh[threadIdx.x] = v;
        __syncthreads();
        for (int off = 1; off < 1024; off <<= 1) {
            int t = (threadIdx.x >= off) ? sh[threadIdx.x - off] : 0;
            __syncthreads();
            sh[threadIdx.x] += t;
            __syncthreads();
        }
        if (i < n) a[i] = sh[threadIdx.x] + carry;
        __syncthreads();
        if (threadIdx.x == 0) carry += sh[1023];
        __syncthreads();
    }
}

__global__ void k_fill(const int* __restrict__ ei, const int* __restrict__ rowptr,
                       int* __restrict__ fill, int* __restrict__ csrc)
{
    int i = blockIdx.x * blockDim.x + threadIdx.x;
    if (i < NEDGE) {
        int d = ei[NEDGE + i];
        int pos = rowptr[d] + atomicAdd(&fill[d], 1);
        csrc[pos] = ei[i];
    }
}

// ---------------- host driver ------------------------------------------------
extern "C" void kernel_launch(void* const* d_in, const int* in_sizes, int n_in,
                              void* d_out, int out_size)
{
    (void)in_sizes; (void)n_in; (void)out_size;
    const float* x0 = (const float*)d_in[0];
    const int* adj[3] = {(const int*)d_in[1], (const int*)d_in[2], (const int*)d_in[3]};
    const float *W0[3], *as0[3], *ad0[3], *b0[3], *W1[3], *as1[3], *ad1[3], *b1[3];
    for (int o = 0; o < 3; ++o) {
        W0[o]  = (const float*)d_in[4  + 4 * o];
        as0[o] = (const float*)d_in[5  + 4 * o];
        ad0[o] = (const float*)d_in[6  + 4 * o];
        b0[o]  = (const float*)d_in[7  + 4 * o];
        W1[o]  = (const float*)d_in[16 + 4 * o];
        as1[o] = (const float*)d_in[17 + 4 * o];
        ad1[o] = (const float*)d_in[18 + 4 * o];
        b1[o]  = (const float*)d_in[19 + 4 * o];
    }
    const float* aggW0 = (const float*)d_in[28];
    const float* aggw0 = (const float*)d_in[29];
    const float* aggW1 = (const float*)d_in[30];
    const float* aggw1 = (const float*)d_in[31];

    float *h, *als, *ald, *st[3], *xb;
    int *rowptr, *csrc, *fill;
    {
        void* p;
        cudaGetSymbolAddress(&p, g_h);      h      = (float*)p;
        cudaGetSymbolAddress(&p, g_als);    als    = (float*)p;
        cudaGetSymbolAddress(&p, g_ald);    ald    = (float*)p;
        cudaGetSymbolAddress(&p, g_s0);     st[0]  = (float*)p;
        cudaGetSymbolAddress(&p, g_s1);     st[1]  = (float*)p;
        cudaGetSymbolAddress(&p, g_s2);     st[2]  = (float*)p;
        cudaGetSymbolAddress(&p, g_x);      xb     = (float*)p;
        cudaGetSymbolAddress(&p, g_rowptr); rowptr = (int*)p;
        cudaGetSymbolAddress(&p, g_csrc);   csrc   = (int*)p;
        cudaGetSymbolAddress(&p, g_fill);   fill   = (int*)p;
    }

    const int TB = 256;
    const int ebl = (NEDGE + TB - 1) / TB;
    const int nwb = (N_NODES * 32 + TB - 1) / TB;   // warp-per-node grids

    // CSR by destination, per order (reused by both layers)
    for (int o = 0; o < 3; ++o) {
        int* rp = rowptr + o * (N_NODES + 1);
        int* cs = csrc + (size_t)o * NEDGE;
        k_zero <<<(N_NODES + 1 + TB - 1) / TB, TB>>>(rp, N_NODES + 1);
        k_count<<<ebl, TB>>>(adj[o], rp);
        k_scan <<<1, 1024>>>(rp, N_NODES + 1);
        k_zero <<<(N_NODES + TB - 1) / TB, TB>>>(fill, N_NODES);
        k_fill <<<ebl, TB>>>(adj[o], rp, fill, cs);
    }

    dim3 gg(1, (N_NODES + 127) / 128);

    // ---- layer 0 (concat=True, C=64, HC=128) ----
    for (int o = 0; o < 3; ++o) {
        k_gemm<<<gg, 256>>>(x0, W0[o], h, N_NODES, F_IN, 128);
        k_al  <<<nwb, TB>>>(h, as0[o], ad0[o], als, ald, 64);
        k_gat <<<nwb, TB>>>(h, als, ald, rowptr + o * (N_NODES + 1),
                            csrc + (size_t)o * NEDGE, b0[o], st[o], 64, 1);
    }
    k_mix<<<(N_NODES * 128 + TB - 1) / TB, TB>>>(st[0], st[1], st[2], aggW0, aggw0,
                                                 xb, N_NODES * 128);

    // ---- layer 1 (concat=False -> head mean, C=40, HC=80) ----
    for (int o = 0; o < 3; ++o) {
        k_gemm<<<gg, 256>>>(xb, W1[o], h, N_NODES, 128, 80);
        k_al  <<<nwb, TB>>>(h, as1[o], ad1[o], als, ald, 40);
        k_gat <<<nwb, TB>>>(h, als, ald, rowptr + o * (N_NODES + 1),
                            csrc + (size_t)o * NEDGE, b1[o], st[o], 40, 0);
    }
    k_mix<<<(N_NODES * 40 + TB - 1) / TB, TB>>>(st[0], st[1], st[2], aggW1, aggw1,
                                                h /*logits*/, N_NODES * 40);
    k_lsm<<<nwb, TB>>>(h, (float*)d_out);
}

// round 7
// speedup vs baseline: 1.0129x; 1.0129x over previous
#include <cuda_runtime.h>
#include <math.h>

#define N_NODES 50000
#define F_IN    500
#define NEDGE   800000

// ---------------- scratch (device globals: no allocation allowed) ----------
__device__ float g_h  [N_NODES * 128];   // GEMM output / logits reuse
__device__ float g_als[N_NODES * 2];
__device__ float g_ald[N_NODES * 2];
__device__ float g_s0 [N_NODES * 128];
__device__ float g_s1 [N_NODES * 128];
__device__ float g_s2 [N_NODES * 128];
__device__ float g_x  [N_NODES * 128];   // layer-0 output / layer-1 input
__device__ int   g_rowptr[3][N_NODES + 1];
__device__ int   g_csrc  [3][NEDGE];
__device__ int   g_fill  [N_NODES];

// ---------------- helpers ---------------------------------------------------
__device__ __forceinline__ float lrelu(float x) { return x > 0.f ? x : 0.2f * x; }
__device__ __forceinline__ float eluf (float x) { return x > 0.f ? x : expm1f(x); }

#define PACK2(d, x, y)  asm("mov.b64 %0, {%1,%2};"      : "=l"(d) : "f"(x), "f"(y))
#define UNPACK2(x, y, d) asm("mov.b64 {%0,%1}, %2;"     : "=f"(x), "=f"(y) : "l"(d))
#define FMA2(d, a, b)   asm("fma.rn.f32x2 %0, %1, %2, %0;" : "+l"(d) : "l"(a), "l"(b))

// ---------------- SGEMM: C[M,Nn] = A[M,K] @ B[K,Nn]  (fp32, f32x2 FMA) -----
// BM=128, BN=128, BK=8, 256 threads, 8x8 per thread.
__global__ __launch_bounds__(256, 2)
void k_gemm(const float* __restrict__ A, const float* __restrict__ B,
            float* __restrict__ C, int M, int K, int Nn)
{
    __shared__ float As[8][128];
    __shared__ float Bs[8][128];
    const int tid  = threadIdx.x;
    const int bm   = blockIdx.y * 128;
    const int bn   = blockIdx.x * 128;
    const int row0 = (tid >> 4) * 8;
    const int col0 = (tid & 15) * 8;

    unsigned long long acc[8][4];
#pragma unroll
    for (int i = 0; i < 8; ++i)
#pragma unroll
        for (int j = 0; j < 4; ++j) acc[i][j] = 0ull;

    const int arow = tid >> 1;
    const int akq  = (tid & 1) * 4;
    const int bkk  = tid >> 5;
    const int bcol = (tid & 31) * 4;
    const int gr   = bm + arow;

    for (int k0 = 0; k0 < K; k0 += 8) {
        float4 av;
        if (gr < M && k0 + akq + 4 <= K) {
            av = *reinterpret_cast<const float4*>(A + (size_t)gr * K + k0 + akq);
        } else {
            av.x = (gr < M && k0 + akq + 0 < K) ? A[(size_t)gr * K + k0 + akq + 0] : 0.f;
            av.y = (gr < M && k0 + akq + 1 < K) ? A[(size_t)gr * K + k0 + akq + 1] : 0.f;
            av.z = (gr < M && k0 + akq + 2 < K) ? A[(size_t)gr * K + k0 + akq + 2] : 0.f;
            av.w = (gr < M && k0 + akq + 3 < K) ? A[(size_t)gr * K + k0 + akq + 3] : 0.f;
        }
        As[akq + 0][arow] = av.x; As[akq + 1][arow] = av.y;
        As[akq + 2][arow] = av.z; As[akq + 3][arow] = av.w;

        float4 bv;
        const int gk = k0 + bkk;
        if (gk < K && bn + bcol + 4 <= Nn) {
            bv = *reinterpret_cast<const float4*>(B + (size_t)gk * Nn + bn + bcol);
        } else {
            bv.x = (gk < K && bn + bcol + 0 < Nn) ? B[(size_t)gk * Nn + bn + bcol + 0] : 0.f;
            bv.y = (gk < K && bn + bcol + 1 < Nn) ? B[(size_t)gk * Nn + bn + bcol + 1] : 0.f;
            bv.z = (gk < K && bn + bcol + 2 < Nn) ? B[(size_t)gk * Nn + bn + bcol + 2] : 0.f;
            bv.w = (gk < K && bn + bcol + 3 < Nn) ? B[(size_t)gk * Nn + bn + bcol + 3] : 0.f;
        }
        *reinterpret_cast<float4*>(&Bs[bkk][bcol]) = bv;
        __syncthreads();

#pragma unroll
        for (int kk = 0; kk < 8; ++kk) {
            float4 a0 = *reinterpret_cast<const float4*>(&As[kk][row0]);
            float4 a1 = *reinterpret_cast<const float4*>(&As[kk][row0 + 4]);
            float4 b0 = *reinterpret_cast<const float4*>(&Bs[kk][col0]);
            float4 b1 = *reinterpret_cast<const float4*>(&Bs[kk][col0 + 4]);
            unsigned long long bp[4], ap;
            PACK2(bp[0], b0.x, b0.y); PACK2(bp[1], b0.z, b0.w);
            PACK2(bp[2], b1.x, b1.y); PACK2(bp[3], b1.z, b1.w);
            float ar[8] = {a0.x, a0.y, a0.z, a0.w, a1.x, a1.y, a1.z, a1.w};
#pragma unroll
            for (int i = 0; i < 8; ++i) {
                PACK2(ap, ar[i], ar[i]);
                FMA2(acc[i][0], ap, bp[0]);
                FMA2(acc[i][1], ap, bp[1]);
                FMA2(acc[i][2], ap, bp[2]);
                FMA2(acc[i][3], ap, bp[3]);
            }
        }
        __syncthreads();
    }

#pragma unroll
    for (int i = 0; i < 8; ++i) {
        int r = bm + row0 + i;
        if (r >= M) break;
        float v[8];
        UNPACK2(v[0], v[1], acc[i][0]);
        UNPACK2(v[2], v[3], acc[i][1]);
        UNPACK2(v[4], v[5], acc[i][2]);
        UNPACK2(v[6], v[7], acc[i][3]);
        if (bn + col0 + 8 <= Nn) {
            *reinterpret_cast<float4*>(C + (size_t)r * Nn + bn + col0)     = make_float4(v[0], v[1], v[2], v[3]);
            *reinterpret_cast<float4*>(C + (size_t)r * Nn + bn + col0 + 4) = make_float4(v[4], v[5], v[6], v[7]);
        } else {
#pragma unroll
            for (int j = 0; j < 8; ++j) {
                int c = bn + col0 + j;
                if (c < Nn) C[(size_t)r * Nn + c] = v[j];
            }
        }
    }
}

// ---------------- attention logit pre-reduction: al_s, al_d [N,2] ----------
__global__ void k_al(const float* __restrict__ h, const float* __restrict__ a_s,
                     const float* __restrict__ a_d, float* __restrict__ als,
                     float* __restrict__ ald, int C)
{
    int w = (blockIdx.x * blockDim.x + threadIdx.x) >> 5;
    if (w >= N_NODES) return;
    int lane = threadIdx.x & 31;
    int HC = 2 * C;
#pragma unroll
    for (int hh = 0; hh < 2; ++hh) {
        float ss = 0.f, sd = 0.f;
        for (int c = lane; c < C; c += 32) {
            float v = h[(size_t)w * HC + hh * C + c];
            ss += v * __ldg(a_s + hh * C + c);
            sd += v * __ldg(a_d + hh * C + c);
        }
#pragma unroll
        for (int o = 16; o; o >>= 1) {
            ss += __shfl_xor_sync(~0u, ss, o);
            sd += __shfl_xor_sync(~0u, sd, o);
        }
        if (lane == 0) { als[w * 2 + hh] = ss; ald[w * 2 + hh] = sd; }
    }
}

// ---------------- fused GAT aggregation: online softmax over CSR -----------
// One warp per dst node; lane owns 4 channels (float4). Self loop included.
__global__ void k_gat(const float* __restrict__ h, const float* __restrict__ als,
                      const float* __restrict__ ald, const int* __restrict__ rowptr,
                      const int* __restrict__ csrc, const float* __restrict__ bias,
                      float* __restrict__ out, int C, int concat)
{
    int n = (blockIdx.x * blockDim.x + threadIdx.x) >> 5;
    if (n >= N_NODES) return;
    const int lane = threadIdx.x & 31;
    const int HC   = 2 * C;
    const int idx  = lane * 4;
    const bool act = idx < HC;
    const int head = (idx >= C) ? 1 : 0;

    const float adh = ald[n * 2 + head];
    float m   = lrelu(als[n * 2 + head] + adh);   // self-loop logit
    float den = 1.f;                              // exp(e_self - m) = 1
    float4 acc = make_float4(0.f, 0.f, 0.f, 0.f);
    if (act) acc = *reinterpret_cast<const float4*>(h + (size_t)n * HC + idx);

    const int p0 = rowptr[n], p1 = rowptr[n + 1];
    for (int p = p0; p < p1; ++p) {
        int s = csrc[p];
        float e  = lrelu(als[s * 2 + head] + adh);
        float nm = fmaxf(m, e);
        float sc = __expf(m - nm);
        float wg = __expf(e - nm);
        den = den * sc + wg;
        m = nm;
        if (act) {
            float4 hv = *reinterpret_cast<const float4*>(h + (size_t)s * HC + idx);
            acc.x = fmaf(acc.x, sc, wg * hv.x);
            acc.y = fmaf(acc.y, sc, wg * hv.y);
            acc.z = fmaf(acc.z, sc, wg * hv.z);
            acc.w = fmaf(acc.w, sc, wg * hv.w);
        }
    }
    float inv = 1.f / (den + 1e-16f);
    float4 v = make_float4(acc.x * inv, acc.y * inv, acc.z * inv, acc.w * inv);

    if (concat) {
        if (act) {
            const float4 b = *reinterpret_cast<const float4*>(bias + idx);
            float4 r;
            r.x = eluf(v.x + b.x); r.y = eluf(v.y + b.y);
            r.z = eluf(v.z + b.z); r.w = eluf(v.w + b.w);
            *reinterpret_cast<float4*>(out + (size_t)n * HC + idx) = r;
        }
    } else {
        int half = C / 4;  // lanes [half, 2*half) hold head 1
        float ox = __shfl_down_sync(~0u, v.x, half);
        float oy = __shfl_down_sync(~0u, v.y, half);
        float oz = __shfl_down_sync(~0u, v.z, half);
        float ow = __shfl_down_sync(~0u, v.w, half);
        if (idx < C) {
            const float4 b = *reinterpret_cast<const float4*>(bias + idx);
            float4 r;
            r.x = eluf(0.5f * (v.x + ox) + b.x);
            r.y = eluf(0.5f * (v.y + oy) + b.y);
            r.z = eluf(0.5f * (v.z + oz) + b.z);
            r.w = eluf(0.5f * (v.w + ow) + b.w);
            *reinterpret_cast<float4*>(out + (size_t)n * C + idx) = r;
        }
    }
}

// ---------------- order mixing: out = sum_j wf[j] * elu(sum_k s_k * W[k,j]) -
__global__ void k_mix(const float* __restrict__ s0, const float* __restrict__ s1,
                      const float* __restrict__ s2, const float* __restrict__ Wm,
                      const float* __restrict__ wf, float* __restrict__ out, int NC)
{
    int i = blockIdx.x * blockDim.x + threadIdx.x;
    if (i >= NC) return;
    float a = s0[i], b = s1[i], c = s2[i];
    float m0 = eluf(a * __ldg(Wm + 0) + b * __ldg(Wm + 3) + c * __ldg(Wm + 6));
    float m1 = eluf(a * __ldg(Wm + 1) + b * __ldg(Wm + 4) + c * __ldg(Wm + 7));
    float m2 = eluf(a * __ldg(Wm + 2) + b * __ldg(Wm + 5) + c * __ldg(Wm + 8));
    out[i] = m0 * __ldg(wf + 0) + m1 * __ldg(wf + 1) + m2 * __ldg(wf + 2);
}

// ---------------- row log-softmax over 40 classes ---------------------------
__global__ void k_lsm(const float* __restrict__ x, float* __restrict__ out)
{
    int n = (blockIdx.x * blockDim.x + threadIdx.x) >> 5;
    if (n >= N_NODES) return;
    int lane = threadIdx.x & 31;
    float v0 = (lane < 40)      ? x[(size_t)n * 40 + lane]      : -1e30f;
    float v1 = (lane + 32 < 40) ? x[(size_t)n * 40 + lane + 32] : -1e30f;
    float mx = fmaxf(v0, v1);
#pragma unroll
    for (int o = 16; o; o >>= 1) mx = fmaxf(mx, __shfl_xor_sync(~0u, mx, o));
    float s = 0.f;
    if (lane < 40)      s += expf(v0 - mx);
    if (lane + 32 < 40) s += expf(v1 - mx);
#pragma unroll
    for (int o = 16; o; o >>= 1) s += __shfl_xor_sync(~0u, s, o);
    float lse = logf(s) + mx;
    if (lane < 40)      out[(size_t)n * 40 + lane]      = v0 - lse;
    if (lane + 32 < 40) out[(size_t)n * 40 + lane + 32] = v1 - lse;
}

// ---------------- CSR build --------------------------------------------------
__global__ void k_zero(int* p, int n)
{
    int i = blockIdx.x * blockDim.x + threadIdx.x;
    if (i < n) p[i] = 0;
}

__global__ void k_count(const int* __restrict__ ei, int* __restrict__ cnt)
{
    int i = blockIdx.x * blockDim.x + threadIdx.x;
    if (i < NEDGE) atomicAdd(&cnt[ei[NEDGE + i] + 1], 1);
}

__global__ void k_scan(int* a, int n)
{
    __shared__ int sh[1024];
    __shared__ int carry;
    if (threadIdx.x == 0) carry = 0;
    __syncthreads();
    for (int base = 0; base < n; base += 1024) {
        int i = base + threadIdx.x;
        int v = (i < n) ? a[i] : 0;
        sh[threadIdx.x] = v;
        __syncthreads();
        for (int off = 1; off < 1024; off <<= 1) {
            int t = (threadIdx.x >= off) ? sh[threadIdx.x - off] : 0;
            __syncthreads();
            sh[threadIdx.x] += t;
            __syncthreads();
        }
        if (i < n) a[i] = sh[threadIdx.x] + carry;
        __syncthreads();
        if (threadIdx.x == 0) carry += sh[1023];
        __syncthreads();
    }
}

__global__ void k_fill(const int* __restrict__ ei, const int* __restrict__ rowptr,
                       int* __restrict__ fill, int* __restrict__ csrc)
{
    int i = blockIdx.x * blockDim.x + threadIdx.x;
    if (i < NEDGE) {
        int d = ei[NEDGE + i];
        int pos = rowptr[d] + atomicAdd(&fill[d], 1);
        csrc[pos] = ei[i];
    }
}

// ---------------- host driver ------------------------------------------------
extern "C" void kernel_launch(void* const* d_in, const int* in_sizes, int n_in,
                              void* d_out, int out_size)
{
    (void)in_sizes; (void)n_in; (void)out_size;
    const float* x0 = (const float*)d_in[0];
    const int* adj[3] = {(const int*)d_in[1], (const int*)d_in[2], (const int*)d_in[3]};
    const float *W0[3], *as0[3], *ad0[3], *b0[3], *W1[3], *as1[3], *ad1[3], *b1[3];
    for (int o = 0; o < 3; ++o) {
        W0[o]  = (const float*)d_in[4  + 4 * o];
        as0[o] = (const float*)d_in[5  + 4 * o];
        ad0[o] = (const float*)d_in[6  + 4 * o];
        b0[o]  = (const float*)d_in[7  + 4 * o];
        W1[o]  = (const float*)d_in[16 + 4 * o];
        as1[o] = (const float*)d_in[17 + 4 * o];
        ad1[o] = (const float*)d_in[18 + 4 * o];
        b1[o]  = (const float*)d_in[19 + 4 * o];
    }
    const float* aggW0 = (const float*)d_in[28];
    const float* aggw0 = (const float*)d_in[29];
    const float* aggW1 = (const float*)d_in[30];
    const float* aggw1 = (const float*)d_in[31];

    float *h, *als, *ald, *st[3], *xb;
    int *rowptr, *csrc, *fill;
    {
        void* p;
        cudaGetSymbolAddress(&p, g_h);      h      = (float*)p;
        cudaGetSymbolAddress(&p, g_als);    als    = (float*)p;
        cudaGetSymbolAddress(&p, g_ald);    ald    = (float*)p;
        cudaGetSymbolAddress(&p, g_s0);     st[0]  = (float*)p;
        cudaGetSymbolAddress(&p, g_s1);     st[1]  = (float*)p;
        cudaGetSymbolAddress(&p, g_s2);     st[2]  = (float*)p;
        cudaGetSymbolAddress(&p, g_x);      xb     = (float*)p;
        cudaGetSymbolAddress(&p, g_rowptr); rowptr = (int*)p;
        cudaGetSymbolAddress(&p, g_csrc);   csrc   = (int*)p;
        cudaGetSymbolAddress(&p, g_fill);   fill   = (int*)p;
    }

    const int TB = 256;
    const int ebl = (NEDGE + TB - 1) / TB;
    const int nwb = (N_NODES * 32 + TB - 1) / TB;   // warp-per-node grids

    // CSR by destination, per order (reused by both layers)
    for (int o = 0; o < 3; ++o) {
        int* rp = rowptr + o * (N_NODES + 1);
        int* cs = csrc + (size_t)o * NEDGE;
        k_zero <<<(N_NODES + 1 + TB - 1) / TB, TB>>>(rp, N_NODES + 1);
        k_count<<<ebl, TB>>>(adj[o], rp);
        k_scan <<<1, 1024>>>(rp, N_NODES + 1);
        k_zero <<<(N_NODES + TB - 1) / TB, TB>>>(fill, N_NODES);
        k_fill <<<ebl, TB>>>(adj[o], rp, fill, cs);
    }

    dim3 gg(1, (N_NODES + 127) / 128);

    // ---- layer 0 (concat=True, C=64, HC=128) ----
    for (int o = 0; o < 3; ++o) {
        k_gemm<<<gg, 256>>>(x0, W0[o], h, N_NODES, F_IN, 128);
        k_al  <<<nwb, TB>>>(h, as0[o], ad0[o], als, ald, 64);
        k_gat <<<nwb, TB>>>(h, als, ald, rowptr + o * (N_NODES + 1),
                            csrc + (size_t)o * NEDGE, b0[o], st[o], 64, 1);
    }
    k_mix<<<(N_NODES * 128 + TB - 1) / TB, TB>>>(st[0], st[1], st[2], aggW0, aggw0,
                                                 xb, N_NODES * 128);

    // ---- layer 1 (concat=False -> head mean, C=40, HC=80) ----
    for (int o = 0; o < 3; ++o) {
        k_gemm<<<gg, 256>>>(xb, W1[o], h, N_NODES, 128, 80);
        k_al  <<<nwb, TB>>>(h, as1[o], ad1[o], als, ald, 40);
        k_gat <<<nwb, TB>>>(h, als, ald, rowptr + o * (N_NODES + 1),
                            csrc + (size_t)o * NEDGE, b1[o], st[o], 40, 0);
    }
    k_mix<<<(N_NODES * 40 + TB - 1) / TB, TB>>>(st[0], st[1], st[2], aggW1, aggw1,
                                                h /*logits*/, N_NODES * 40);
    k_lsm<<<nwb, TB>>>(h, (float*)d_out);
}

// round 8
// speedup vs baseline: 1.3909x; 1.3731x over previous
#include <cuda_runtime.h>
#include <math.h>

#define N_NODES 50000
#define F_IN    500
#define NEDGE   800000

// ---------------- scratch (device globals: no allocation allowed) ----------
__device__ float g_h  [N_NODES * 384];       // fused GEMM output (layer0: 384, layer1: 240)
__device__ float g_als[3 * N_NODES * 2];
__device__ float g_ald[3 * N_NODES * 2];
__device__ float g_s0 [N_NODES * 128];
__device__ float g_s1 [N_NODES * 128];
__device__ float g_s2 [N_NODES * 128];
__device__ float g_x  [N_NODES * 128];       // layer-0 mix output / layer-1 input / logits
__device__ float g_Wp [F_IN * 384];          // packed weights
__device__ int   g_rowptr[3 * (N_NODES + 1)];
__device__ int   g_csrc  [3][NEDGE];
__device__ int   g_fill  [3 * N_NODES];

// ---------------- helpers ---------------------------------------------------
__device__ __forceinline__ float lrelu(float x) { return x > 0.f ? x : 0.2f * x; }
__device__ __forceinline__ float eluf (float x) { return x > 0.f ? x : expm1f(x); }

#define PACK2(d, x, y)   asm("mov.b64 %0, {%1,%2};"      : "=l"(d) : "f"(x), "f"(y))
#define UNPACK2(x, y, d) asm("mov.b64 {%0,%1}, %2;"      : "=f"(x), "=f"(y) : "l"(d))
#define FMA2(d, a, b)    asm("fma.rn.f32x2 %0, %1, %2, %0;" : "+l"(d) : "l"(a), "l"(b))

// ---------------- weight packer: out[k, o*Np+j] = Wo[k, j] ------------------
__global__ void k_pack(const float* __restrict__ W0, const float* __restrict__ W1,
                       const float* __restrict__ W2, float* __restrict__ out,
                       int K, int Np)
{
    int i = blockIdx.x * blockDim.x + threadIdx.x;
    int total = K * 3 * Np;
    if (i >= total) return;
    int k = i / (3 * Np);
    int r = i % (3 * Np);
    int o = r / Np, j = r % Np;
    const float* W = (o == 0) ? W0 : (o == 1) ? W1 : W2;
    out[i] = W[k * Np + j];
}

// ---------------- SGEMM (double-buffered): C[M,Nn] = A[M,K] @ B[K,Nn] -------
// BM=128, BN=128, BK=8, 256 threads, 8x8/thread, f32x2 accumulate.
__global__ __launch_bounds__(256, 2)
void k_gemm(const float* __restrict__ A, const float* __restrict__ B,
            float* __restrict__ C, int M, int K, int Nn)
{
    __shared__ float As[2][8][128];
    __shared__ float Bs[2][8][128];
    const int tid  = threadIdx.x;
    const int bm   = blockIdx.y * 128;
    const int bn   = blockIdx.x * 128;
    const int row0 = (tid >> 4) * 8;
    const int col0 = (tid & 15) * 8;

    unsigned long long acc[8][4];
#pragma unroll
    for (int i = 0; i < 8; ++i)
#pragma unroll
        for (int j = 0; j < 4; ++j) acc[i][j] = 0ull;

    const int arow = tid >> 1;
    const int akq  = (tid & 1) * 4;
    const int bkk  = tid >> 5;
    const int bcol = (tid & 31) * 4;
    const int gr   = bm + arow;

#define LOAD_TILE(k0, av, bv)                                                       \
    {                                                                               \
        if (gr < M && (k0) + akq + 4 <= K) {                                        \
            av = *reinterpret_cast<const float4*>(A + (size_t)gr * K + (k0) + akq); \
        } else {                                                                    \
            av.x = (gr < M && (k0) + akq + 0 < K) ? A[(size_t)gr * K + (k0) + akq + 0] : 0.f; \
            av.y = (gr < M && (k0) + akq + 1 < K) ? A[(size_t)gr * K + (k0) + akq + 1] : 0.f; \
            av.z = (gr < M && (k0) + akq + 2 < K) ? A[(size_t)gr * K + (k0) + akq + 2] : 0.f; \
            av.w = (gr < M && (k0) + akq + 3 < K) ? A[(size_t)gr * K + (k0) + akq + 3] : 0.f; \
        }                                                                           \
        const int gk = (k0) + bkk;                                                  \
        if (gk < K && bn + bcol + 4 <= Nn) {                                        \
            bv = *reinterpret_cast<const float4*>(B + (size_t)gk * Nn + bn + bcol); \
        } else {                                                                    \
            bv.x = (gk < K && bn + bcol + 0 < Nn) ? B[(size_t)gk * Nn + bn + bcol + 0] : 0.f; \
            bv.y = (gk < K && bn + bcol + 1 < Nn) ? B[(size_t)gk * Nn + bn + bcol + 1] : 0.f; \
            bv.z = (gk < K && bn + bcol + 2 < Nn) ? B[(size_t)gk * Nn + bn + bcol + 2] : 0.f; \
            bv.w = (gk < K && bn + bcol + 3 < Nn) ? B[(size_t)gk * Nn + bn + bcol + 3] : 0.f; \
        }                                                                           \
    }

#define STORE_TILE(buf, av, bv)                               \
    {                                                         \
        As[buf][akq + 0][arow] = av.x;                        \
        As[buf][akq + 1][arow] = av.y;                        \
        As[buf][akq + 2][arow] = av.z;                        \
        As[buf][akq + 3][arow] = av.w;                        \
        *reinterpret_cast<float4*>(&Bs[buf][bkk][bcol]) = bv; \
    }

#define COMPUTE_TILE(buf)                                                          \
    {                                                                              \
        _Pragma("unroll")                                                          \
        for (int kk = 0; kk < 8; ++kk) {                                           \
            float4 a0 = *reinterpret_cast<const float4*>(&As[buf][kk][row0]);      \
            float4 a1 = *reinterpret_cast<const float4*>(&As[buf][kk][row0 + 4]);  \
            float4 c0 = *reinterpret_cast<const float4*>(&Bs[buf][kk][col0]);      \
            float4 c1 = *reinterpret_cast<const float4*>(&Bs[buf][kk][col0 + 4]);  \
            unsigned long long bp[4], ap;                                          \
            PACK2(bp[0], c0.x, c0.y); PACK2(bp[1], c0.z, c0.w);                    \
            PACK2(bp[2], c1.x, c1.y); PACK2(bp[3], c1.z, c1.w);                    \
            float ar[8] = {a0.x, a0.y, a0.z, a0.w, a1.x, a1.y, a1.z, a1.w};        \
            _Pragma("unroll")                                                      \
            for (int i = 0; i < 8; ++i) {                                          \
                PACK2(ap, ar[i], ar[i]);                                           \
                FMA2(acc[i][0], ap, bp[0]);                                        \
                FMA2(acc[i][1], ap, bp[1]);                                        \
                FMA2(acc[i][2], ap, bp[2]);                                        \
                FMA2(acc[i][3], ap, bp[3]);                                        \
            }                                                                      \
        }                                                                          \
    }

    float4 av, bv;
    LOAD_TILE(0, av, bv);
    STORE_TILE(0, av, bv);
    __syncthreads();
    int cur = 0;
    for (int k0 = 8; k0 < K; k0 += 8) {
        float4 av2, bv2;
        LOAD_TILE(k0, av2, bv2);
        COMPUTE_TILE(cur);
        STORE_TILE(cur ^ 1, av2, bv2);
        __syncthreads();
        cur ^= 1;
    }
    COMPUTE_TILE(cur);

#pragma unroll
    for (int i = 0; i < 8; ++i) {
        int r = bm + row0 + i;
        if (r >= M) break;
        float v[8];
        UNPACK2(v[0], v[1], acc[i][0]);
        UNPACK2(v[2], v[3], acc[i][1]);
        UNPACK2(v[4], v[5], acc[i][2]);
        UNPACK2(v[6], v[7], acc[i][3]);
        if (bn + col0 + 8 <= Nn) {
            *reinterpret_cast<float4*>(C + (size_t)r * Nn + bn + col0)     = make_float4(v[0], v[1], v[2], v[3]);
            *reinterpret_cast<float4*>(C + (size_t)r * Nn + bn + col0 + 4) = make_float4(v[4], v[5], v[6], v[7]);
        } else {
#pragma unroll
            for (int j = 0; j < 8; ++j) {
                int c = bn + col0 + j;
                if (c < Nn) C[(size_t)r * Nn + c] = v[j];
            }
        }
    }
#undef LOAD_TILE
#undef STORE_TILE
#undef COMPUTE_TILE
}

// ---------------- fused attention logit pre-reduction over 3 orders ---------
__global__ void k_al3(const float* __restrict__ h, int RS, int C,
                      const float* as0, const float* as1, const float* as2,
                      const float* ad0, const float* ad1, const float* ad2,
                      float* __restrict__ als, float* __restrict__ ald)
{
    int w = (blockIdx.x * blockDim.x + threadIdx.x) >> 5;
    if (w >= N_NODES) return;
    int lane = threadIdx.x & 31;
    const float* row = h + (size_t)w * RS;
#pragma unroll
    for (int o = 0; o < 3; ++o) {
        const float* A_s = (o == 0) ? as0 : (o == 1) ? as1 : as2;
        const float* A_d = (o == 0) ? ad0 : (o == 1) ? ad1 : ad2;
#pragma unroll
        for (int hh = 0; hh < 2; ++hh) {
            float ss = 0.f, sd = 0.f;
            for (int c = lane; c < C; c += 32) {
                float v = row[o * 2 * C + hh * C + c];
                ss += v * __ldg(A_s + hh * C + c);
                sd += v * __ldg(A_d + hh * C + c);
            }
#pragma unroll
            for (int off = 16; off; off >>= 1) {
                ss += __shfl_xor_sync(~0u, ss, off);
                sd += __shfl_xor_sync(~0u, sd, off);
            }
            if (!lane) {
                als[o * 2 * N_NODES + w * 2 + hh] = ss;
                ald[o * 2 * N_NODES + w * 2 + hh] = sd;
            }
        }
    }
}

// ---------------- fused GAT aggregation: online softmax, batched prefetch ---
// gridDim.y = order. One warp per dst node; lane owns 4 channels.
__global__ void k_gat3(const float* __restrict__ hall, int RS, int C,
                       const int* __restrict__ rowptr_all, const int* __restrict__ csrc_all,
                       const float* __restrict__ als_all, const float* __restrict__ ald_all,
                       const float* b0f, const float* b1f, const float* b2f,
                       float* o0, float* o1, float* o2, int concat)
{
    int n = (blockIdx.x * blockDim.x + threadIdx.x) >> 5;
    if (n >= N_NODES) return;
    const int o = blockIdx.y;
    const int* rowptr = rowptr_all + o * (N_NODES + 1);
    const int* csrc   = csrc_all + (size_t)o * NEDGE;
    const float* als  = als_all + o * 2 * N_NODES;
    const float* ald  = ald_all + o * 2 * N_NODES;
    const float* bias = (o == 0) ? b0f : (o == 1) ? b1f : b2f;
    float* out        = (o == 0) ? o0  : (o == 1) ? o1  : o2;
    const float* h    = hall + o * 2 * C;   // column window for this order

    const int lane = threadIdx.x & 31;
    const int HC   = 2 * C;
    const int idx  = lane * 4;
    const bool act = idx < HC;
    const int head = (idx >= C) ? 1 : 0;

    const float adh = ald[n * 2 + head];
    float m   = lrelu(als[n * 2 + head] + adh);   // self-loop logit
    float den = 1.f;
    float4 acc = make_float4(0.f, 0.f, 0.f, 0.f);
    if (act) acc = *reinterpret_cast<const float4*>(h + (size_t)n * RS + idx);

    const int p0 = rowptr[n], p1 = rowptr[n + 1];
    for (int p = p0; p < p1; p += 8) {
        int sv[8]; float ev[8]; float4 hv[8];
#pragma unroll
        for (int i = 0; i < 8; ++i) {
            int q = p + i;
            sv[i] = csrc[q < p1 ? q : p1 - 1];
        }
#pragma unroll
        for (int i = 0; i < 8; ++i) ev[i] = als[sv[i] * 2 + head];
        if (act) {
#pragma unroll
            for (int i = 0; i < 8; ++i)
                hv[i] = *reinterpret_cast<const float4*>(h + (size_t)sv[i] * RS + idx);
        }
        const int cnt = min(8, p1 - p);
#pragma unroll
        for (int i = 0; i < 8; ++i) {
            if (i < cnt) {
                float e  = lrelu(ev[i] + adh);
                float nm = fmaxf(m, e);
                float sc = __expf(m - nm);
                float wg = __expf(e - nm);
                den = den * sc + wg;
                m = nm;
                if (act) {
                    acc.x = fmaf(acc.x, sc, wg * hv[i].x);
                    acc.y = fmaf(acc.y, sc, wg * hv[i].y);
                    acc.z = fmaf(acc.z, sc, wg * hv[i].z);
                    acc.w = fmaf(acc.w, sc, wg * hv[i].w);
                }
            }
        }
    }
    float inv = 1.f / (den + 1e-16f);
    float4 v = make_float4(acc.x * inv, acc.y * inv, acc.z * inv, acc.w * inv);

    if (concat) {
        if (act) {
            const float4 b = *reinterpret_cast<const float4*>(bias + idx);
            float4 r;
            r.x = eluf(v.x + b.x); r.y = eluf(v.y + b.y);
            r.z = eluf(v.z + b.z); r.w = eluf(v.w + b.w);
            *reinterpret_cast<float4*>(out + (size_t)n * HC + idx) = r;
        }
    } else {
        int half = C / 4;
        float ox = __shfl_down_sync(~0u, v.x, half);
        float oy = __shfl_down_sync(~0u, v.y, half);
        float oz = __shfl_down_sync(~0u, v.z, half);
        float ow = __shfl_down_sync(~0u, v.w, half);
        if (idx < C) {
            const float4 b = *reinterpret_cast<const float4*>(bias + idx);
            float4 r;
            r.x = eluf(0.5f * (v.x + ox) + b.x);
            r.y = eluf(0.5f * (v.y + oy) + b.y);
            r.z = eluf(0.5f * (v.z + oz) + b.z);
            r.w = eluf(0.5f * (v.w + ow) + b.w);
            *reinterpret_cast<float4*>(out + (size_t)n * C + idx) = r;
        }
    }
}

// ---------------- order mixing ----------------------------------------------
__global__ void k_mix(const float* __restrict__ s0, const float* __restrict__ s1,
                      const float* __restrict__ s2, const float* __restrict__ Wm,
                      const float* __restrict__ wf, float* __restrict__ out, int NC)
{
    int i = blockIdx.x * blockDim.x + threadIdx.x;
    if (i >= NC) return;
    float a = s0[i], b = s1[i], c = s2[i];
    float m0 = eluf(a * __ldg(Wm + 0) + b * __ldg(Wm + 3) + c * __ldg(Wm + 6));
    float m1 = eluf(a * __ldg(Wm + 1) + b * __ldg(Wm + 4) + c * __ldg(Wm + 7));
    float m2 = eluf(a * __ldg(Wm + 2) + b * __ldg(Wm + 5) + c * __ldg(Wm + 8));
    out[i] = m0 * __ldg(wf + 0) + m1 * __ldg(wf + 1) + m2 * __ldg(wf + 2);
}

// ---------------- row log-softmax over 40 classes ---------------------------
__global__ void k_lsm(const float* __restrict__ x, float* __restrict__ out)
{
    int n = (blockIdx.x * blockDim.x + threadIdx.x) >> 5;
    if (n >= N_NODES) return;
    int lane = threadIdx.x & 31;
    float v0 = (lane < 40)      ? x[(size_t)n * 40 + lane]      : -1e30f;
    float v1 = (lane + 32 < 40) ? x[(size_t)n * 40 + lane + 32] : -1e30f;
    float mx = fmaxf(v0, v1);
#pragma unroll
    for (int o = 16; o; o >>= 1) mx = fmaxf(mx, __shfl_xor_sync(~0u, mx, o));
    float s = 0.f;
    if (lane < 40)      s += expf(v0 - mx);
    if (lane + 32 < 40) s += expf(v1 - mx);
#pragma unroll
    for (int o = 16; o; o >>= 1) s += __shfl_xor_sync(~0u, s, o);
    float lse = logf(s) + mx;
    if (lane < 40)      out[(size_t)n * 40 + lane]      = v0 - lse;
    if (lane + 32 < 40) out[(size_t)n * 40 + lane + 32] = v1 - lse;
}

// ---------------- CSR build (fused over orders) ------------------------------
__global__ void k_zero2(int* a, int na, int* b, int nb)
{
    int i = blockIdx.x * blockDim.x + threadIdx.x;
    if (i < na) a[i] = 0;
    else if (i - na < nb) b[i - na] = 0;
}

__global__ void k_count3(const int* e0, const int* e1, const int* e2,
                         int* __restrict__ rowptr_all)
{
    int o = blockIdx.y;
    const int* ei = (o == 0) ? e0 : (o == 1) ? e1 : e2;
    int i = blockIdx.x * blockDim.x + threadIdx.x;
    if (i < NEDGE) atomicAdd(&rowptr_all[o * (N_NODES + 1) + ei[NEDGE + i] + 1], 1);
}

__global__ void k_scan3(int* __restrict__ rowptr_all)
{
    int* a = rowptr_all + blockIdx.x * (N_NODES + 1);
    const int n = N_NODES + 1;
    __shared__ int wsum[32];
    __shared__ int carry;
    int tid = threadIdx.x, lane = tid & 31, wid = tid >> 5;
    if (tid == 0) carry = 0;
    __syncthreads();
    for (int base = 0; base < n; base += 1024) {
        int i = base + tid;
        int v = (i < n) ? a[i] : 0;
#pragma unroll
        for (int off = 1; off < 32; off <<= 1) {
            int t = __shfl_up_sync(~0u, v, off);
            if (lane >= off) v += t;
        }
        if (lane == 31) wsum[wid] = v;
        __syncthreads();
        if (wid == 0) {
            int w = wsum[lane];
#pragma unroll
            for (int off = 1; off < 32; off <<= 1) {
                int t = __shfl_up_sync(~0u, w, off);
                if (lane >= off) w += t;
            }
            wsum[lane] = w;
        }
        __syncthreads();
        int add = carry + (wid ? wsum[wid - 1] : 0);
        if (i < n) a[i] = v + add;
        __syncthreads();
        if (tid == 0) carry += wsum[31];
        __syncthreads();
    }
}

__global__ void k_fill3(const int* e0, const int* e1, const int* e2,
                        const int* __restrict__ rowptr_all, int* __restrict__ fill,
                        int* __restrict__ csrc_all)
{
    int o = blockIdx.y;
    const int* ei = (o == 0) ? e0 : (o == 1) ? e1 : e2;
    int i = blockIdx.x * blockDim.x + threadIdx.x;
    if (i < NEDGE) {
        int d = ei[NEDGE + i];
        int pos = rowptr_all[o * (N_NODES + 1) + d] + atomicAdd(&fill[o * N_NODES + d], 1);
        csrc_all[(size_t)o * NEDGE + pos] = ei[i];
    }
}

// ---------------- host driver ------------------------------------------------
extern "C" void kernel_launch(void* const* d_in, const int* in_sizes, int n_in,
                              void* d_out, int out_size)
{
    (void)in_sizes; (void)n_in; (void)out_size;
    const float* x0 = (const float*)d_in[0];
    const int* e0 = (const int*)d_in[1];
    const int* e1 = (const int*)d_in[2];
    const int* e2 = (const int*)d_in[3];
    const float *W0[3], *as0[3], *ad0[3], *b0[3], *W1[3], *as1[3], *ad1[3], *b1[3];
    for (int o = 0; o < 3; ++o) {
        W0[o]  = (const float*)d_in[4  + 4 * o];
        as0[o] = (const float*)d_in[5  + 4 * o];
        ad0[o] = (const float*)d_in[6  + 4 * o];
        b0[o]  = (const float*)d_in[7  + 4 * o];
        W1[o]  = (const float*)d_in[16 + 4 * o];
        as1[o] = (const float*)d_in[17 + 4 * o];
        ad1[o] = (const float*)d_in[18 + 4 * o];
        b1[o]  = (const float*)d_in[19 + 4 * o];
    }
    const float* aggW0 = (const float*)d_in[28];
    const float* aggw0 = (const float*)d_in[29];
    const float* aggW1 = (const float*)d_in[30];
    const float* aggw1 = (const float*)d_in[31];

    float *h, *als, *ald, *st[3], *xb, *Wp;
    int *rowptr, *csrc, *fill;
    {
        void* p;
        cudaGetSymbolAddress(&p, g_h);      h      = (float*)p;
        cudaGetSymbolAddress(&p, g_als);    als    = (float*)p;
        cudaGetSymbolAddress(&p, g_ald);    ald    = (float*)p;
        cudaGetSymbolAddress(&p, g_s0);     st[0]  = (float*)p;
        cudaGetSymbolAddress(&p, g_s1);     st[1]  = (float*)p;
        cudaGetSymbolAddress(&p, g_s2);     st[2]  = (float*)p;
        cudaGetSymbolAddress(&p, g_x);      xb     = (float*)p;
        cudaGetSymbolAddress(&p, g_Wp);     Wp     = (float*)p;
        cudaGetSymbolAddress(&p, g_rowptr); rowptr = (int*)p;
        cudaGetSymbolAddress(&p, g_csrc);   csrc   = (int*)p;
        cudaGetSymbolAddress(&p, g_fill);   fill   = (int*)p;
    }

    const int TB  = 256;
    const int ebl = (NEDGE + TB - 1) / TB;
    const int nwb = (N_NODES * 32 + TB - 1) / TB;   // warp-per-node grids
    const int gwb = (N_NODES * 32 / 256);           // 6250, exact

    // ---- CSR build: 4 launches ----
    {
        int na = 3 * (N_NODES + 1), nb = 3 * N_NODES;
        k_zero2 <<<(na + nb + TB - 1) / TB, TB>>>(rowptr, na, fill, nb);
        k_count3<<<dim3(ebl, 3), TB>>>(e0, e1, e2, rowptr);
        k_scan3 <<<3, 1024>>>(rowptr);
        k_fill3 <<<dim3(ebl, 3), TB>>>(e0, e1, e2, rowptr, fill, csrc);
    }

    const int rb = (N_NODES + 127) / 128;   // 391 row blocks

    // ---- layer 0 (concat=True, C=64, HC=128, fused N=384) ----
    k_pack<<<(F_IN * 384 + TB - 1) / TB, TB>>>(W0[0], W0[1], W0[2], Wp, F_IN, 128);
    k_gemm<<<dim3(3, rb), 256>>>(x0, Wp, h, N_NODES, F_IN, 384);   // launch #5: profiled
    k_al3 <<<nwb, TB>>>(h, 384, 64, as0[0], as0[1], as0[2], ad0[0], ad0[1], ad0[2], als, ald);
    k_gat3<<<dim3(gwb, 3), 256>>>(h, 384, 64, rowptr, csrc, als, ald,
                                  b0[0], b0[1], b0[2], st[0], st[1], st[2], 1);
    k_mix <<<(N_NODES * 128 + TB - 1) / TB, TB>>>(st[0], st[1], st[2], aggW0, aggw0,
                                                  xb, N_NODES * 128);

    // ---- layer 1 (concat=False -> head mean, C=40, HC=80, fused N=240) ----
    k_pack<<<(128 * 240 + TB - 1) / TB, TB>>>(W1[0], W1[1], W1[2], Wp, 128, 80);
    k_gemm<<<dim3(2, rb), 256>>>(xb, Wp, h, N_NODES, 128, 240);
    k_al3 <<<nwb, TB>>>(h, 240, 40, as1[0], as1[1], as1[2], ad1[0], ad1[1], ad1[2], als, ald);
    k_gat3<<<dim3(gwb, 3), 256>>>(h, 240, 40, rowptr, csrc, als, ald,
                                  b1[0], b1[1], b1[2], st[0], st[1], st[2], 0);
    k_mix <<<(N_NODES * 40 + TB - 1) / TB, TB>>>(st[0], st[1], st[2], aggW1, aggw1,
                                                 xb, N_NODES * 40);
    k_lsm <<<nwb, TB>>>(xb, (float*)d_out);
}